// round 1
// baseline (speedup 1.0000x reference)
#include <cuda_runtime.h>
#include <math.h>

// Problem constants (fixed by the reference setup_inputs)
#define BB 4
#define NN 16384
#define CC 128
#define MM 128
#define NS 512
#define ROW (3 + CC)      // 131 floats per pooled row
#define BLOCK 256
#define NWARP (BLOCK / 32)

__global__ __launch_bounds__(BLOCK)
void roipool3d_kernel(const float* __restrict__ points,   // [B,N,3]
                      const float* __restrict__ feats,    // [B,N,C]
                      const float* __restrict__ boxes,    // [B,M,7]
                      float* __restrict__ out)            // [B*M*NS*ROW] feats, then [B*M] flags
{
    const int bm = blockIdx.x;            // b*MM + m
    const int b  = bm / MM;
    const float* pts = points + (size_t)b * NN * 3;
    const float* ft  = feats  + (size_t)b * NN * CC;
    const float* box = boxes  + (size_t)bm * 7;

    __shared__ int   s_idx[NS];
    __shared__ int   s_row[NS];
    __shared__ int   s_wcnt[NWARP];
    __shared__ int   s_cnt;
    __shared__ float s_box[7];

    const int tid = threadIdx.x;
    if (tid < 7) s_box[tid] = box[tid];
    if (tid == 0) s_cnt = 0;
    __syncthreads();

    const float cx = s_box[0], cy = s_box[1], cz = s_box[2];
    // dims = d + 2*EXTRA_WIDTH (EXTRA_WIDTH=1.0), then half = dims*0.5 — exact op order
    const float hx = __fmul_rn(__fadd_rn(s_box[3], 2.0f), 0.5f);
    const float hy = __fmul_rn(__fadd_rn(s_box[4], 2.0f), 0.5f);
    const float hz = __fmul_rn(__fadd_rn(s_box[5], 2.0f), 0.5f);
    // high-accuracy f32 cos/sin (match XLA's ~correctly-rounded libm)
    const double hd = (double)s_box[6];
    const float ch = (float)cos(hd);
    const float sh = (float)sin(hd);

    // ---- Phase 1: ordered compaction of inside-point indices, early exit at NS ----
    const int lane = tid & 31;
    const int w    = tid >> 5;
    const unsigned lmask = (lane == 31) ? 0x7fffffffu : ((1u << lane) - 1u);

    for (int base = 0; base < NN; base += BLOCK) {
        const int i = base + tid;
        const float x = pts[i * 3 + 0];
        const float y = pts[i * 3 + 1];
        const float z = pts[i * 3 + 2];
        const float sx = x - cx;
        const float sy = y - cy;
        const float sz = z - cz;
        // non-fused, matching reference elementwise arithmetic
        const float lx = __fadd_rn(__fmul_rn(sx, ch), __fmul_rn(sy, sh));
        const float ly = __fadd_rn(__fmul_rn(-sx, sh), __fmul_rn(sy, ch));
        const bool pred = (fabsf(lx) < hx) & (fabsf(ly) < hy) & (fabsf(sz) < hz);

        const unsigned ball = __ballot_sync(0xffffffffu, pred);
        if (lane == 0) s_wcnt[w] = __popc(ball);
        __syncthreads();

        int off = s_cnt;
        #pragma unroll
        for (int j = 0; j < NWARP; j++)
            off += (j < w) ? s_wcnt[j] : 0;
        off += __popc(ball & lmask);
        if (pred && off < NS) s_idx[off] = i;
        __syncthreads();

        if (tid == 0) {
            int tot = 0;
            #pragma unroll
            for (int j = 0; j < NWARP; j++) tot += s_wcnt[j];
            s_cnt = min(NS, s_cnt + tot);
        }
        __syncthreads();
        if (s_cnt >= NS) break;   // consistent across block (read after barrier)
    }

    const int cnt = s_cnt;
    const size_t obase = (size_t)bm * NS * ROW;
    const size_t flag_base = (size_t)BB * MM * NS * ROW;

    // ---- Phase 2: gather / zero-fill ----
    if (cnt == 0) {
        for (int e = tid; e < NS * ROW; e += BLOCK)
            out[obase + e] = 0.0f;
        if (tid == 0) out[flag_base + bm] = 1.0f;
        return;
    }

    // precompute wrapped source rows
    for (int k = tid; k < NS; k += BLOCK)
        s_row[k] = s_idx[(cnt >= NS) ? k : (k % cnt)];
    __syncthreads();

    for (int e = tid; e < NS * ROW; e += BLOCK) {
        const int k = e / ROW;
        const int c = e - k * ROW;
        const int idx = s_row[k];
        float v;
        if (c < 3) v = pts[idx * 3 + c];
        else       v = ft[(size_t)idx * CC + (c - 3)];
        out[obase + e] = v;
    }
    if (tid == 0) out[flag_base + bm] = 0.0f;
}

extern "C" void kernel_launch(void* const* d_in, const int* in_sizes, int n_in,
                              void* d_out, int out_size) {
    const float* points = (const float*)d_in[0];   // [4,16384,3]
    const float* feats  = (const float*)d_in[1];   // [4,16384,128]
    const float* boxes  = (const float*)d_in[2];   // [4,128,7]
    float* out = (float*)d_out;
    roipool3d_kernel<<<BB * MM, BLOCK>>>(points, feats, boxes, out);
}

// round 2
// speedup vs baseline: 1.3996x; 1.3996x over previous
#include <cuda_runtime.h>
#include <math.h>

// Problem constants (fixed by the reference setup_inputs)
#define BB 4
#define NN 16384
#define CC 128
#define MM 128
#define NS 512
#define ROW (3 + CC)        // 131 floats per pooled row
#define NBOX (BB * MM)      // 512
#define BLOCK 256
#define NWARP (BLOCK / 32)
#define SEG (NN / NWARP)    // 2048 points per warp
#define SEGIT (SEG / 32)    // 64 ballot iterations per warp

// Scratch: wrapped source-row indices per box + inside-count per box
__device__ int g_rows[NBOX * NS];
__device__ int g_cnt[NBOX];

// ---------------- Kernel 1: ordered compaction (1 CTA per box) ----------------
__global__ __launch_bounds__(BLOCK)
void k1_compact(const float* __restrict__ points,   // [B,N,3]
                const float* __restrict__ boxes,    // [B,M,7]
                float* __restrict__ out)            // flags live at tail of out
{
    const int bm = blockIdx.x;
    const int b  = bm >> 7;                          // / MM
    const float* pts = points + (size_t)b * NN * 3;
    const float* box = boxes  + (size_t)bm * 7;

    __shared__ unsigned s_ball[NWARP][SEGIT];        // 8*64*4 = 2KB
    __shared__ int      s_wcnt[NWARP];
    __shared__ int      s_idx[NS];
    __shared__ float    s_box[7];

    const int tid  = threadIdx.x;
    const int w    = tid >> 5;
    const int lane = tid & 31;
    const unsigned lmask = (lane == 31) ? 0x7fffffffu : ((1u << lane) - 1u);

    if (tid < 7) s_box[tid] = box[tid];
    __syncthreads();

    const float cx = s_box[0], cy = s_box[1], cz = s_box[2];
    const float hx = __fmul_rn(__fadd_rn(s_box[3], 2.0f), 0.5f);
    const float hy = __fmul_rn(__fadd_rn(s_box[4], 2.0f), 0.5f);
    const float hz = __fmul_rn(__fadd_rn(s_box[5], 2.0f), 0.5f);
    const double hd = (double)s_box[6];
    const float ch = (float)cos(hd);
    const float sh = (float)sin(hd);

    // ---- Pass A: per-warp ballots over its contiguous segment (no barriers) ----
    const int seg = w * SEG;
    int mycnt = 0;
    #pragma unroll 4
    for (int it = 0; it < SEGIT; ++it) {
        const int i = seg + it * 32 + lane;
        const float x = pts[i * 3 + 0];
        const float y = pts[i * 3 + 1];
        const float z = pts[i * 3 + 2];
        const float sx = x - cx;
        const float sy = y - cy;
        const float sz = z - cz;
        const float lx = __fadd_rn(__fmul_rn(sx, ch), __fmul_rn(sy, sh));
        const float ly = __fadd_rn(__fmul_rn(-sx, sh), __fmul_rn(sy, ch));
        const bool pred = (fabsf(lx) < hx) & (fabsf(ly) < hy) & (fabsf(sz) < hz);
        const unsigned ball = __ballot_sync(0xffffffffu, pred);
        if (lane == 0) s_ball[w][it] = ball;
        mycnt += __popc(ball);
    }
    if (lane == 0) s_wcnt[w] = mycnt;
    __syncthreads();

    // warp prefix + total
    int off = 0, cnt = 0;
    #pragma unroll
    for (int j = 0; j < NWARP; j++) {
        const int c = s_wcnt[j];
        if (j < w) off += c;
        cnt += c;
    }

    // ---- Pass B: replay ballots from smem, emit ordered indices < NS ----
    for (int it = 0; it < SEGIT && off < NS; ++it) {
        const unsigned ball = s_ball[w][it];
        if (ball & (1u << lane)) {
            const int pos = off + __popc(ball & lmask);
            if (pos < NS) s_idx[pos] = seg + it * 32 + lane;
        }
        off += __popc(ball);
    }
    __syncthreads();

    const size_t flag_base = (size_t)NBOX * NS * ROW;
    if (cnt == 0) {
        if (tid == 0) { g_cnt[bm] = 0; out[flag_base + bm] = 1.0f; }
        return;
    }
    // wrapped rows: k % cnt only matters when cnt < NS
    for (int k = tid; k < NS; k += BLOCK)
        g_rows[bm * NS + k] = s_idx[(cnt >= NS) ? k : (k % cnt)];
    if (tid == 0) { g_cnt[bm] = cnt; out[flag_base + bm] = 0.0f; }
}

// ---------------- Kernel 2: gather (4 CTAs per box, 1 warp per row) ----------------
#define ROWS_PER_CTA 128

__global__ __launch_bounds__(BLOCK)
void k2_gather(const float* __restrict__ points,    // [B,N,3]
               const float* __restrict__ feats,     // [B,N,C]
               float* __restrict__ out)
{
    const int part = blockIdx.x & 3;
    const int bm   = blockIdx.x >> 2;
    const int b    = bm >> 7;
    const int k0   = part * ROWS_PER_CTA;

    const float*  pts = points + (size_t)b * NN * 3;
    const float4* ft4 = (const float4*)(feats + (size_t)b * NN * CC);

    const int tid  = threadIdx.x;
    const int w    = tid >> 5;
    const int lane = tid & 31;

    const int cnt = g_cnt[bm];
    const size_t obase = (size_t)bm * NS * ROW + (size_t)k0 * ROW;

    if (cnt == 0) {
        for (int e = tid; e < ROWS_PER_CTA * ROW; e += BLOCK)
            out[obase + e] = 0.0f;
        return;
    }

    __shared__ int s_row[ROWS_PER_CTA];
    if (tid < ROWS_PER_CTA) s_row[tid] = g_rows[bm * NS + k0 + tid];
    __syncthreads();

    #pragma unroll 2
    for (int r = w; r < ROWS_PER_CTA; r += NWARP) {
        const int idx = s_row[r];
        const size_t base = obase + (size_t)r * ROW;
        const float4 f = ft4[(size_t)idx * 32 + lane];   // coalesced 512B row
        if (lane < 3) out[base + lane] = pts[idx * 3 + lane];
        float* o = (float*)&out[base + 3 + 4 * lane];
        o[0] = f.x; o[1] = f.y; o[2] = f.z; o[3] = f.w;
    }
}

extern "C" void kernel_launch(void* const* d_in, const int* in_sizes, int n_in,
                              void* d_out, int out_size) {
    const float* points = (const float*)d_in[0];   // [4,16384,3]
    const float* feats  = (const float*)d_in[1];   // [4,16384,128]
    const float* boxes  = (const float*)d_in[2];   // [4,128,7]
    float* out = (float*)d_out;
    k1_compact<<<NBOX, BLOCK>>>(points, boxes, out);
    k2_gather<<<NBOX * (NS / ROWS_PER_CTA), BLOCK>>>(points, feats, out);
}

// round 3
// speedup vs baseline: 1.7082x; 1.2205x over previous
#include <cuda_runtime.h>
#include <math.h>

#define BB 4
#define NN 16384
#define CC 128
#define MM 128
#define NS 512
#define ROW (3 + CC)        // 131 floats per pooled row
#define NBOX (BB * MM)      // 512
#define BLOCK 256
#define NWARP (BLOCK / 32)
#define WORDS (NN / 32)     // 512 mask words per box

// per-box inside-mask bitmap: g_mask[box][word], word = point/32
__device__ unsigned g_mask[NBOX * WORDS];

// ---------------- Kernel A: mask (points x boxes, point-resident) ----------------
// grid = BB * 64 chunks of 256 points; each thread holds one point, loops 128 boxes.
__global__ __launch_bounds__(BLOCK)
void kA_mask(const float* __restrict__ points,   // [B,N,3]
             const float* __restrict__ boxes)    // [B,M,7]
{
    const int b  = blockIdx.x >> 6;
    const int pc = blockIdx.x & 63;               // 256-point chunk
    const int tid  = threadIdx.x;
    const int w    = tid >> 5;
    const int lane = tid & 31;

    __shared__ float4 s_prm[MM * 2];              // {cx,cy,cz,hx},{hy,hz,ch,sh}

    // precompute per-box params (threads 0..127)
    if (tid < MM) {
        const float* bx = boxes + (size_t)(b * MM + tid) * 7;
        const float cx = bx[0], cy = bx[1], cz = bx[2];
        const float hx = __fmul_rn(__fadd_rn(bx[3], 2.0f), 0.5f);
        const float hy = __fmul_rn(__fadd_rn(bx[4], 2.0f), 0.5f);
        const float hz = __fmul_rn(__fadd_rn(bx[5], 2.0f), 0.5f);
        const double hd = (double)bx[6];
        const float ch = (float)cos(hd);
        const float sh = (float)sin(hd);
        s_prm[tid * 2 + 0] = make_float4(cx, cy, cz, hx);
        s_prm[tid * 2 + 1] = make_float4(hy, hz, ch, sh);
    }

    const int i = pc * BLOCK + tid;               // point index within batch
    const float* p = points + ((size_t)b * NN + i) * 3;
    const float x = p[0], y = p[1], z = p[2];
    __syncthreads();

    unsigned* gm = g_mask + (size_t)(b * MM) * WORDS + pc * NWARP + w;

    #pragma unroll 4
    for (int bi = 0; bi < MM; ++bi) {
        const float4 A = s_prm[bi * 2 + 0];
        const float4 Bp = s_prm[bi * 2 + 1];
        const float sx = x - A.x;
        const float sy = y - A.y;
        const float sz = z - A.z;
        const float lx = __fadd_rn(__fmul_rn(sx, Bp.z), __fmul_rn(sy, Bp.w));
        const float ly = __fadd_rn(__fmul_rn(-sx, Bp.w), __fmul_rn(sy, Bp.z));
        const bool pred = (fabsf(lx) < A.w) & (fabsf(ly) < Bp.x) & (fabsf(sz) < Bp.y);
        const unsigned ball = __ballot_sync(0xffffffffu, pred);
        if (lane == 0) gm[(size_t)bi * WORDS] = ball;
    }
}

// ---------------- Kernel B: scan masks + gather (1 CTA per box) ----------------
__global__ __launch_bounds__(BLOCK)
void kB_gather(const float* __restrict__ points,    // [B,N,3]
               const float* __restrict__ feats,     // [B,N,C]
               float* __restrict__ out)
{
    const int bm = blockIdx.x;
    const int b  = bm >> 7;
    const int tid  = threadIdx.x;
    const int w    = tid >> 5;
    const int lane = tid & 31;

    __shared__ int s_idx[NS];
    __shared__ int s_row[NS];
    __shared__ int s_wtot[NWARP];
    __shared__ int s_cnt;

    // each thread owns mask words 2t, 2t+1 (points t*64 .. t*64+63)
    const unsigned* gm = g_mask + (size_t)bm * WORDS;
    const unsigned w0 = gm[tid * 2 + 0];
    const unsigned w1 = gm[tid * 2 + 1];
    const int c0 = __popc(w0);
    const int c1 = __popc(w1);
    const int myc = c0 + c1;

    // block-wide exclusive prefix of myc
    int scan = myc;
    #pragma unroll
    for (int d = 1; d < 32; d <<= 1) {
        const int v = __shfl_up_sync(0xffffffffu, scan, d);
        if (lane >= d) scan += v;
    }
    if (lane == 31) s_wtot[w] = scan;
    __syncthreads();
    int wbase = 0, tot = 0;
    #pragma unroll
    for (int j = 0; j < NWARP; ++j) {
        const int c = s_wtot[j];
        if (j < w) wbase += c;
        tot += c;
    }
    const int excl = wbase + scan - myc;

    // emit ordered indices < NS
    if (excl < NS) {
        int p = excl;
        unsigned ww = w0;
        while (ww) {
            const int bit = __ffs(ww) - 1;
            ww &= ww - 1;
            if (p < NS) s_idx[p] = tid * 64 + bit;
            ++p;
        }
        p = excl + c0;
        ww = w1;
        while (ww) {
            const int bit = __ffs(ww) - 1;
            ww &= ww - 1;
            if (p < NS) s_idx[p] = tid * 64 + 32 + bit;
            ++p;
        }
    }
    if (tid == 0) s_cnt = tot;
    __syncthreads();

    const int cnt = s_cnt;
    const size_t obase = (size_t)bm * NS * ROW;
    const size_t flag_base = (size_t)NBOX * NS * ROW;

    if (cnt == 0) {
        float4* o4 = (float4*)(out + obase);      // region is 16B-aligned, 16768 float4
        for (int e = tid; e < NS * ROW / 4; e += BLOCK)
            o4[e] = make_float4(0.f, 0.f, 0.f, 0.f);
        if (tid == 0) out[flag_base + bm] = 1.0f;
        return;
    }

    // wrapped source rows
    for (int k = tid; k < NS; k += BLOCK)
        s_row[k] = s_idx[(cnt >= NS) ? k : (k % cnt)];
    __syncthreads();

    const float* pts = points + (size_t)b * NN * 3;
    const float* ft  = feats  + (size_t)b * NN * CC;

    // one warp per row; strided lanes -> every LDG/STG fully coalesced
    #pragma unroll 2
    for (int k = w; k < NS; k += NWARP) {
        const int idx = s_row[k];
        const size_t base = obase + (size_t)k * ROW;
        const float* src = ft + (size_t)idx * CC;
        float* dst = out + base + 3;
        if (lane < 3) out[base + lane] = pts[idx * 3 + lane];
        #pragma unroll
        for (int j = 0; j < 4; ++j)
            dst[lane + 32 * j] = src[lane + 32 * j];
    }
    if (tid == 0) out[flag_base + bm] = 0.0f;
}

extern "C" void kernel_launch(void* const* d_in, const int* in_sizes, int n_in,
                              void* d_out, int out_size) {
    const float* points = (const float*)d_in[0];   // [4,16384,3]
    const float* feats  = (const float*)d_in[1];   // [4,16384,128]
    const float* boxes  = (const float*)d_in[2];   // [4,128,7]
    float* out = (float*)d_out;
    kA_mask<<<BB * 64, BLOCK>>>(points, boxes);
    kB_gather<<<NBOX, BLOCK>>>(points, feats, out);
}

// round 4
// speedup vs baseline: 1.9576x; 1.1460x over previous
#include <cuda_runtime.h>
#include <math.h>

#define BB 4
#define NN 16384
#define CC 128
#define MM 128
#define NS 512
#define ROW (3 + CC)        // 131 floats per pooled row
#define NBOX (BB * MM)      // 512
#define BLOCK 256
#define NWARP (BLOCK / 32)
#define WORDS (NN / 32)     // 512 mask words per box
#define ASPLIT 4            // box-loop split in kA
#define BOXCHUNK (MM / ASPLIT)   // 32 boxes per kA CTA
#define GPARTS 8            // gather CTAs per box
#define GROWS (NS / GPARTS) // 64 rows per gather CTA

__device__ unsigned g_mask[NBOX * WORDS];   // inside-mask bitmap
__device__ int g_rows[NBOX * NS];           // wrapped source row per output slot
__device__ int g_cnt[NBOX];

// ---------------- Kernel A: mask (point-resident, boxes split 4-way) ----------------
__global__ __launch_bounds__(BLOCK)
void kA_mask(const float* __restrict__ points,   // [B,N,3]
             const float* __restrict__ boxes)    // [B,M,7]
{
    const int bs  = blockIdx.x;
    const int sb  = bs & (ASPLIT - 1);            // box sub-block
    const int pc  = (bs >> 2) & 63;               // 256-point chunk
    const int b   = bs >> 8;
    const int tid  = threadIdx.x;
    const int w    = tid >> 5;
    const int lane = tid & 31;
    const int box0 = sb * BOXCHUNK;

    __shared__ float4 s_prm[BOXCHUNK * 2];        // {cx,cy,cz,hx},{hy,hz,ch,sh}

    if (tid < BOXCHUNK) {
        const float* bx = boxes + (size_t)(b * MM + box0 + tid) * 7;
        const float hx = __fmul_rn(__fadd_rn(bx[3], 2.0f), 0.5f);
        const float hy = __fmul_rn(__fadd_rn(bx[4], 2.0f), 0.5f);
        const float hz = __fmul_rn(__fadd_rn(bx[5], 2.0f), 0.5f);
        const double hd = (double)bx[6];
        s_prm[tid * 2 + 0] = make_float4(bx[0], bx[1], bx[2], hx);
        s_prm[tid * 2 + 1] = make_float4(hy, hz, (float)cos(hd), (float)sin(hd));
    }

    const int i = pc * BLOCK + tid;
    const float* p = points + ((size_t)b * NN + i) * 3;
    const float x = p[0], y = p[1], z = p[2];
    __syncthreads();

    unsigned* gm = g_mask + (size_t)(b * MM + box0) * WORDS + pc * NWARP + w;

    #pragma unroll 4
    for (int bi = 0; bi < BOXCHUNK; ++bi) {
        const float4 A  = s_prm[bi * 2 + 0];
        const float4 Bp = s_prm[bi * 2 + 1];
        const float sx = x - A.x;
        const float sy = y - A.y;
        const float sz = z - A.z;
        const float lx = __fadd_rn(__fmul_rn(sx, Bp.z), __fmul_rn(sy, Bp.w));
        const float ly = __fadd_rn(__fmul_rn(-sx, Bp.w), __fmul_rn(sy, Bp.z));
        const bool pred = (fabsf(lx) < A.w) & (fabsf(ly) < Bp.x) & (fabsf(sz) < Bp.y);
        const unsigned ball = __ballot_sync(0xffffffffu, pred);
        if (lane == 0) gm[(size_t)bi * WORDS] = ball;
    }
}

// ---------------- Kernel B: scan masks -> wrapped row indices (1 CTA per box) ----------------
__global__ __launch_bounds__(BLOCK)
void kB_scan(float* __restrict__ out)
{
    const int bm = blockIdx.x;
    const int tid  = threadIdx.x;
    const int w    = tid >> 5;
    const int lane = tid & 31;

    __shared__ int s_idx[NS];
    __shared__ int s_wtot[NWARP];
    __shared__ int s_cnt;

    const unsigned* gm = g_mask + (size_t)bm * WORDS;
    const unsigned w0 = gm[tid * 2 + 0];
    const unsigned w1 = gm[tid * 2 + 1];
    const int c0 = __popc(w0);
    const int myc = c0 + __popc(w1);

    int scan = myc;
    #pragma unroll
    for (int d = 1; d < 32; d <<= 1) {
        const int v = __shfl_up_sync(0xffffffffu, scan, d);
        if (lane >= d) scan += v;
    }
    if (lane == 31) s_wtot[w] = scan;
    __syncthreads();
    int wbase = 0, tot = 0;
    #pragma unroll
    for (int j = 0; j < NWARP; ++j) {
        const int c = s_wtot[j];
        if (j < w) wbase += c;
        tot += c;
    }
    const int excl = wbase + scan - myc;

    if (excl < NS) {
        int p = excl;
        unsigned ww = w0;
        while (ww) {
            const int bit = __ffs(ww) - 1;
            ww &= ww - 1;
            if (p < NS) s_idx[p] = tid * 64 + bit;
            ++p;
        }
        p = excl + c0;
        ww = w1;
        while (ww) {
            const int bit = __ffs(ww) - 1;
            ww &= ww - 1;
            if (p < NS) s_idx[p] = tid * 64 + 32 + bit;
            ++p;
        }
    }
    if (tid == 0) s_cnt = tot;
    __syncthreads();

    const int cnt = s_cnt;
    const size_t flag_base = (size_t)NBOX * NS * ROW;
    if (tid == 0) {
        g_cnt[bm] = cnt;
        out[flag_base + bm] = (cnt == 0) ? 1.0f : 0.0f;
    }
    if (cnt == 0) return;
    for (int k = tid; k < NS; k += BLOCK)
        g_rows[bm * NS + k] = s_idx[(cnt >= NS) ? k : (k % cnt)];
}

// ---------------- Kernel C: gather (8 CTAs per box, warp per row) ----------------
__global__ __launch_bounds__(BLOCK)
void kC_gather(const float* __restrict__ points,
               const float* __restrict__ feats,
               float* __restrict__ out)
{
    const int part = blockIdx.x & (GPARTS - 1);
    const int bm   = blockIdx.x >> 3;
    const int b    = bm >> 7;
    const int k0   = part * GROWS;
    const int tid  = threadIdx.x;
    const int w    = tid >> 5;
    const int lane = tid & 31;

    const int cnt = g_cnt[bm];
    const size_t obase = (size_t)bm * NS * ROW + (size_t)k0 * ROW;

    if (cnt == 0) {
        for (int e = tid; e < GROWS * ROW; e += BLOCK)
            out[obase + e] = 0.0f;
        return;
    }

    __shared__ int s_row[GROWS];
    if (tid < GROWS) s_row[tid] = g_rows[bm * NS + k0 + tid];
    __syncthreads();

    const float* pts = points + (size_t)b * NN * 3;
    const float* ft  = feats  + (size_t)b * NN * CC;

    #pragma unroll 2
    for (int k = w; k < GROWS; k += NWARP) {
        const int idx = s_row[k];
        const size_t base = obase + (size_t)k * ROW;
        const float* src = ft + (size_t)idx * CC;
        float* dst = out + base + 3;
        if (lane < 3) out[base + lane] = pts[idx * 3 + lane];
        #pragma unroll
        for (int j = 0; j < 4; ++j)
            dst[lane + 32 * j] = src[lane + 32 * j];
    }
}

extern "C" void kernel_launch(void* const* d_in, const int* in_sizes, int n_in,
                              void* d_out, int out_size) {
    const float* points = (const float*)d_in[0];   // [4,16384,3]
    const float* feats  = (const float*)d_in[1];   // [4,16384,128]
    const float* boxes  = (const float*)d_in[2];   // [4,128,7]
    float* out = (float*)d_out;
    kA_mask<<<BB * 64 * ASPLIT, BLOCK>>>(points, boxes);
    kB_scan<<<NBOX, BLOCK>>>(out);
    kC_gather<<<NBOX * GPARTS, BLOCK>>>(points, feats, out);
}

// round 5
// speedup vs baseline: 2.1103x; 1.0780x over previous
#include <cuda_runtime.h>
#include <math.h>

#define BB 4
#define NN 16384
#define CC 128
#define MM 128
#define NS 512
#define ROW (3 + CC)        // 131 floats per pooled row
#define NBOX (BB * MM)      // 512
#define BLOCK 256
#define NWARP (BLOCK / 32)
#define WORDS (NN / 32)     // 512 mask words per box
#define ASPLIT 8            // box-loop split in kA
#define BOXCHUNK (MM / ASPLIT)   // 16 boxes per kA CTA
#define PCHUNK 512          // points per kA CTA (2 per thread)
#define GPARTS 8            // gather CTAs per box
#define GROWS (NS / GPARTS) // 64 rows per gather CTA

__device__ unsigned g_mask[NBOX * WORDS];   // inside-mask bitmap [box][word]

// ---------------- Kernel A: mask (point-resident, 2 points/thread) ----------------
// grid = BB(4) * 32 point-chunks * ASPLIT(8) = 1024
__global__ __launch_bounds__(BLOCK)
void kA_mask(const float* __restrict__ points,   // [B,N,3]
             const float* __restrict__ boxes)    // [B,M,7]
{
    const int bs   = blockIdx.x;
    const int sb   = bs & (ASPLIT - 1);
    const int pc   = (bs >> 3) & 31;              // 512-point chunk
    const int b    = bs >> 8;
    const int tid  = threadIdx.x;
    const int w    = tid >> 5;
    const int lane = tid & 31;
    const int box0 = sb * BOXCHUNK;

    __shared__ float4 s_prm[BOXCHUNK * 2];        // {cx,cy,cz,hx},{hy,hz,ch,sh}

    if (tid < BOXCHUNK) {
        const float* bx = boxes + (size_t)(b * MM + box0 + tid) * 7;
        const float hx = __fmul_rn(__fadd_rn(bx[3], 2.0f), 0.5f);
        const float hy = __fmul_rn(__fadd_rn(bx[4], 2.0f), 0.5f);
        const float hz = __fmul_rn(__fadd_rn(bx[5], 2.0f), 0.5f);
        const double hd = (double)bx[6];
        s_prm[tid * 2 + 0] = make_float4(bx[0], bx[1], bx[2], hx);
        s_prm[tid * 2 + 1] = make_float4(hy, hz, (float)cos(hd), (float)sin(hd));
    }

    const int i0 = pc * PCHUNK + tid;             // point 0
    const int i1 = i0 + BLOCK;                    // point 1
    const float* p0 = points + ((size_t)b * NN + i0) * 3;
    const float* p1 = points + ((size_t)b * NN + i1) * 3;
    const float x0 = p0[0], y0 = p0[1], z0 = p0[2];
    const float x1 = p1[0], y1 = p1[1], z1 = p1[2];
    __syncthreads();

    // word index for point group 0: pc*16 + w ; group 1: pc*16 + 8 + w
    unsigned* gm = g_mask + (size_t)(b * MM + box0) * WORDS + pc * (PCHUNK / 32) + w;

    #pragma unroll 4
    for (int bi = 0; bi < BOXCHUNK; ++bi) {
        const float4 A  = s_prm[bi * 2 + 0];
        const float4 Bp = s_prm[bi * 2 + 1];

        const float sx0 = x0 - A.x, sy0 = y0 - A.y, sz0 = z0 - A.z;
        const float lx0 = __fadd_rn(__fmul_rn(sx0, Bp.z), __fmul_rn(sy0, Bp.w));
        const float ly0 = __fadd_rn(__fmul_rn(-sx0, Bp.w), __fmul_rn(sy0, Bp.z));
        const bool pr0 = (fabsf(lx0) < A.w) & (fabsf(ly0) < Bp.x) & (fabsf(sz0) < Bp.y);

        const float sx1 = x1 - A.x, sy1 = y1 - A.y, sz1 = z1 - A.z;
        const float lx1 = __fadd_rn(__fmul_rn(sx1, Bp.z), __fmul_rn(sy1, Bp.w));
        const float ly1 = __fadd_rn(__fmul_rn(-sx1, Bp.w), __fmul_rn(sy1, Bp.z));
        const bool pr1 = (fabsf(lx1) < A.w) & (fabsf(ly1) < Bp.x) & (fabsf(sz1) < Bp.y);

        const unsigned b0 = __ballot_sync(0xffffffffu, pr0);
        const unsigned b1 = __ballot_sync(0xffffffffu, pr1);
        if (lane == 0) {
            gm[(size_t)bi * WORDS]     = b0;
            gm[(size_t)bi * WORDS + 8] = b1;
        }
    }
}

// ---------------- Kernel BC: fused scan + gather (8 CTAs per box) ----------------
__global__ __launch_bounds__(BLOCK)
void kBC_gather(const float* __restrict__ points,
                const float* __restrict__ feats,
                float* __restrict__ out)
{
    const int part = blockIdx.x & (GPARTS - 1);
    const int bm   = blockIdx.x >> 3;
    const int b    = bm >> 7;
    const int k0   = part * GROWS;
    const int tid  = threadIdx.x;
    const int w    = tid >> 5;
    const int lane = tid & 31;

    __shared__ int s_idx[NS];
    __shared__ int s_row[GROWS];
    __shared__ int s_wtot[NWARP];
    __shared__ int s_cnt;

    // ---- scan: each thread owns mask words 2t, 2t+1 ----
    const unsigned* gm = g_mask + (size_t)bm * WORDS;
    const unsigned w0 = gm[tid * 2 + 0];
    const unsigned w1 = gm[tid * 2 + 1];
    const int c0 = __popc(w0);
    const int myc = c0 + __popc(w1);

    int scan = myc;
    #pragma unroll
    for (int d = 1; d < 32; d <<= 1) {
        const int v = __shfl_up_sync(0xffffffffu, scan, d);
        if (lane >= d) scan += v;
    }
    if (lane == 31) s_wtot[w] = scan;
    __syncthreads();
    int wbase = 0, tot = 0;
    #pragma unroll
    for (int j = 0; j < NWARP; ++j) {
        const int c = s_wtot[j];
        if (j < w) wbase += c;
        tot += c;
    }
    const int excl = wbase + scan - myc;

    if (excl < NS && myc) {
        int p = excl;
        unsigned ww = w0;
        while (ww) {
            const int bit = __ffs(ww) - 1;
            ww &= ww - 1;
            if (p < NS) s_idx[p] = tid * 64 + bit;
            ++p;
        }
        p = excl + c0;
        ww = w1;
        while (ww) {
            const int bit = __ffs(ww) - 1;
            ww &= ww - 1;
            if (p < NS) s_idx[p] = tid * 64 + 32 + bit;
            ++p;
        }
    }
    if (tid == 0) s_cnt = tot;
    __syncthreads();

    const int cnt = s_cnt;
    const size_t obase = (size_t)bm * NS * ROW + (size_t)k0 * ROW;
    const size_t flag_base = (size_t)NBOX * NS * ROW;

    if (cnt == 0) {
        float4* o4 = (float4*)(out + obase);      // 16B-aligned region
        for (int e = tid; e < GROWS * ROW / 4; e += BLOCK)
            o4[e] = make_float4(0.f, 0.f, 0.f, 0.f);
        if (part == 0 && tid == 0) out[flag_base + bm] = 1.0f;
        return;
    }

    // wrapped rows for this part only
    if (tid < GROWS) {
        const int k = k0 + tid;
        s_row[tid] = s_idx[(cnt >= NS) ? k : (k % cnt)];
    }
    if (part == 0 && tid == 0) out[flag_base + bm] = 0.0f;
    __syncthreads();

    const float* pts = points + (size_t)b * NN * 3;
    const float* ft  = feats  + (size_t)b * NN * CC;

    #pragma unroll 2
    for (int k = w; k < GROWS; k += NWARP) {
        const int idx = s_row[k];
        const size_t base = obase + (size_t)k * ROW;
        const float* src = ft + (size_t)idx * CC;
        float* dst = out + base + 3;
        if (lane < 3) out[base + lane] = pts[idx * 3 + lane];
        #pragma unroll
        for (int j = 0; j < 4; ++j)
            dst[lane + 32 * j] = src[lane + 32 * j];
    }
}

extern "C" void kernel_launch(void* const* d_in, const int* in_sizes, int n_in,
                              void* d_out, int out_size) {
    const float* points = (const float*)d_in[0];   // [4,16384,3]
    const float* feats  = (const float*)d_in[1];   // [4,16384,128]
    const float* boxes  = (const float*)d_in[2];   // [4,128,7]
    float* out = (float*)d_out;
    kA_mask<<<BB * 32 * ASPLIT, BLOCK>>>(points, boxes);
    kBC_gather<<<NBOX * GPARTS, BLOCK>>>(points, feats, out);
}

// round 6
// speedup vs baseline: 2.1260x; 1.0075x over previous
#include <cuda_runtime.h>
#include <math.h>

#define BB 4
#define NN 16384
#define CC 128
#define MM 128
#define NS 512
#define ROW (3 + CC)        // 131 floats per pooled row
#define NBOX (BB * MM)      // 512
#define BLOCK 256
#define NWARP (BLOCK / 32)
#define WORDS (NN / 32)     // 512 mask words per box
#define ASPLIT 16           // box-loop split in kA
#define BOXCHUNK (MM / ASPLIT)   // 8 boxes per kA CTA
#define PCHUNK 1024         // points per kA CTA (4 per thread)
#define PCHUNKS (NN / PCHUNK)    // 16
#define GPARTS 8            // gather CTAs per box
#define GROWS (NS / GPARTS) // 64 rows per gather CTA

__device__ unsigned g_mask[NBOX * WORDS];   // inside-mask bitmap [box][word]

// ---------------- Kernel A: mask (point-resident, 4 points/thread) ----------------
// grid = BB(4) * PCHUNKS(16) * ASPLIT(16) = 1024
__global__ __launch_bounds__(BLOCK)
void kA_mask(const float* __restrict__ points,   // [B,N,3]
             const float* __restrict__ boxes)    // [B,M,7]
{
    const int bs   = blockIdx.x;
    const int sb   = bs & (ASPLIT - 1);
    const int pc   = (bs >> 4) & (PCHUNKS - 1);
    const int b    = bs >> 8;
    const int tid  = threadIdx.x;
    const int w    = tid >> 5;
    const int lane = tid & 31;
    const int box0 = sb * BOXCHUNK;

    __shared__ float4 s_prm[BOXCHUNK * 2];        // {cx,cy,cz,hx},{hy,hz,ch,sh}

    if (tid < BOXCHUNK) {
        const float* bx = boxes + (size_t)(b * MM + box0 + tid) * 7;
        const float hx = __fmul_rn(__fadd_rn(bx[3], 2.0f), 0.5f);
        const float hy = __fmul_rn(__fadd_rn(bx[4], 2.0f), 0.5f);
        const float hz = __fmul_rn(__fadd_rn(bx[5], 2.0f), 0.5f);
        const double hd = (double)bx[6];
        s_prm[tid * 2 + 0] = make_float4(bx[0], bx[1], bx[2], hx);
        s_prm[tid * 2 + 1] = make_float4(hy, hz, (float)cos(hd), (float)sin(hd));
    }

    float px[4], py[4], pz[4];
    const int i0 = pc * PCHUNK + tid;
    #pragma unroll
    for (int g = 0; g < 4; ++g) {
        const float* p = points + ((size_t)b * NN + i0 + g * BLOCK) * 3;
        px[g] = p[0]; py[g] = p[1]; pz[g] = p[2];
    }
    __syncthreads();

    // word for point-group g: pc*(PCHUNK/32) + g*8 + w
    unsigned* gm = g_mask + (size_t)(b * MM + box0) * WORDS + pc * (PCHUNK / 32) + w;

    #pragma unroll 2
    for (int bi = 0; bi < BOXCHUNK; ++bi) {
        const float4 A  = s_prm[bi * 2 + 0];
        const float4 Bp = s_prm[bi * 2 + 1];
        unsigned ball[4];
        #pragma unroll
        for (int g = 0; g < 4; ++g) {
            const float sx = px[g] - A.x;
            const float sy = py[g] - A.y;
            const float sz = pz[g] - A.z;
            const float lx = __fadd_rn(__fmul_rn(sx, Bp.z), __fmul_rn(sy, Bp.w));
            const float ly = __fadd_rn(__fmul_rn(-sx, Bp.w), __fmul_rn(sy, Bp.z));
            const bool pred = (fabsf(lx) < A.w) & (fabsf(ly) < Bp.x) & (fabsf(sz) < Bp.y);
            ball[g] = __ballot_sync(0xffffffffu, pred);
        }
        if (lane == 0) {
            #pragma unroll
            for (int g = 0; g < 4; ++g)
                gm[(size_t)bi * WORDS + g * 8] = ball[g];
        }
    }
}

// ---------------- Kernel BC: fused scan + gather (8 CTAs per box) ----------------
__global__ __launch_bounds__(BLOCK)
void kBC_gather(const float* __restrict__ points,
                const float* __restrict__ feats,
                float* __restrict__ out)
{
    const int part = blockIdx.x & (GPARTS - 1);
    const int bm   = blockIdx.x >> 3;
    const int b    = bm >> 7;
    const int k0   = part * GROWS;
    const int tid  = threadIdx.x;
    const int w    = tid >> 5;
    const int lane = tid & 31;

    __shared__ int s_idx[NS];
    __shared__ int s_row[GROWS];
    __shared__ int s_wtot[NWARP];
    __shared__ int s_cnt;

    // ---- scan: each thread owns mask words 2t, 2t+1 ----
    const unsigned* gm = g_mask + (size_t)bm * WORDS;
    const unsigned w0 = gm[tid * 2 + 0];
    const unsigned w1 = gm[tid * 2 + 1];
    const int c0 = __popc(w0);
    const int myc = c0 + __popc(w1);

    int scan = myc;
    #pragma unroll
    for (int d = 1; d < 32; d <<= 1) {
        const int v = __shfl_up_sync(0xffffffffu, scan, d);
        if (lane >= d) scan += v;
    }
    if (lane == 31) s_wtot[w] = scan;
    __syncthreads();
    int wbase = 0, tot = 0;
    #pragma unroll
    for (int j = 0; j < NWARP; ++j) {
        const int c = s_wtot[j];
        if (j < w) wbase += c;
        tot += c;
    }
    const int excl = wbase + scan - myc;

    if (excl < NS && myc) {
        int p = excl;
        unsigned ww = w0;
        while (ww) {
            const int bit = __ffs(ww) - 1;
            ww &= ww - 1;
            if (p < NS) s_idx[p] = tid * 64 + bit;
            ++p;
        }
        p = excl + c0;
        ww = w1;
        while (ww) {
            const int bit = __ffs(ww) - 1;
            ww &= ww - 1;
            if (p < NS) s_idx[p] = tid * 64 + 32 + bit;
            ++p;
        }
    }
    if (tid == 0) s_cnt = tot;
    __syncthreads();

    const int cnt = s_cnt;
    const size_t obase = (size_t)bm * NS * ROW + (size_t)k0 * ROW;
    const size_t flag_base = (size_t)NBOX * NS * ROW;

    if (cnt == 0) {
        float4* o4 = (float4*)(out + obase);      // 16B-aligned region
        for (int e = tid; e < GROWS * ROW / 4; e += BLOCK)
            o4[e] = make_float4(0.f, 0.f, 0.f, 0.f);
        if (part == 0 && tid == 0) out[flag_base + bm] = 1.0f;
        return;
    }

    if (tid < GROWS) {
        const int k = k0 + tid;
        s_row[tid] = s_idx[(cnt >= NS) ? k : (k % cnt)];
    }
    if (part == 0 && tid == 0) out[flag_base + bm] = 0.0f;
    __syncthreads();

    const float* pts = points + (size_t)b * NN * 3;
    const float* ft  = feats  + (size_t)b * NN * CC;

    // 2 rows per iteration per warp: 8 feature LDGs + 2 point LDGs in flight
    // before any store (MLP ~10), all accesses coalesced.
    #pragma unroll
    for (int i = 0; i < GROWS / (2 * NWARP); ++i) {
        const int r0 = 2 * (w + NWARP * i);
        const int r1 = r0 + 1;
        const int ia = s_row[r0];
        const int ib = s_row[r1];
        const float* sa = ft + (size_t)ia * CC;
        const float* sb = ft + (size_t)ib * CC;

        float av[4], bv[4];
        #pragma unroll
        for (int j = 0; j < 4; ++j) av[j] = sa[lane + 32 * j];
        #pragma unroll
        for (int j = 0; j < 4; ++j) bv[j] = sb[lane + 32 * j];
        float pa = 0.f, pb = 0.f;
        if (lane < 3) { pa = pts[ia * 3 + lane]; pb = pts[ib * 3 + lane]; }

        const size_t basea = obase + (size_t)r0 * ROW;
        const size_t baseb = obase + (size_t)r1 * ROW;
        if (lane < 3) { out[basea + lane] = pa; out[baseb + lane] = pb; }
        float* da = out + basea + 3;
        float* db = out + baseb + 3;
        #pragma unroll
        for (int j = 0; j < 4; ++j) da[lane + 32 * j] = av[j];
        #pragma unroll
        for (int j = 0; j < 4; ++j) db[lane + 32 * j] = bv[j];
    }
}

extern "C" void kernel_launch(void* const* d_in, const int* in_sizes, int n_in,
                              void* d_out, int out_size) {
    const float* points = (const float*)d_in[0];   // [4,16384,3]
    const float* feats  = (const float*)d_in[1];   // [4,16384,128]
    const float* boxes  = (const float*)d_in[2];   // [4,128,7]
    float* out = (float*)d_out;
    kA_mask<<<BB * PCHUNKS * ASPLIT, BLOCK>>>(points, boxes);
    kBC_gather<<<NBOX * GPARTS, BLOCK>>>(points, feats, out);
}